// round 7
// baseline (speedup 1.0000x reference)
#include <cuda_runtime.h>
#include <math.h>

#define NN   1024
#define OUTD 128
#define TJ   32
#define NT   32
#define RPAD 132
#define VPAD 132
#define WP   34
#define OPAD 132

#define ABSM 0x7FFFFFFF7FFFFFFFULL

typedef unsigned long long u64;

// ---- scratch ----
__device__ __align__(16) float g_L[NN * OUTD];
__device__ __align__(16) float g_R[NN * OUTD];
__device__ __align__(16) float g_V[NN * OUTD];
__device__ __align__(16) float g_aR[4 * NN];   // [h][j]

__constant__ __align__(16) float c_a[32];

// ---- f32x2 helpers ----
__device__ __forceinline__ u64 f2add(u64 a, u64 b) {
    u64 d; asm("add.rn.f32x2 %0,%1,%2;" : "=l"(d) : "l"(a), "l"(b)); return d;
}
__device__ __forceinline__ u64 f2fma(u64 a, u64 b, u64 c) {
    u64 d; asm("fma.rn.f32x2 %0,%1,%2,%3;" : "=l"(d) : "l"(a), "l"(b), "l"(c)); return d;
}
__device__ __forceinline__ u64 f2pack(float x, float y) {
    u64 d; asm("mov.b64 %0,{%1,%2};" : "=l"(d) : "f"(x), "f"(y)); return d;
}
__device__ __forceinline__ float2 f2unpack(u64 v) {
    float x, y; asm("mov.b64 {%0,%1},%2;" : "=f"(x), "=f"(y) : "l"(v));
    return make_float2(x, y);
}
__device__ __forceinline__ u64 a2c(int k) { return *(const u64*)&c_a[2 * k]; }

// =====================================================================
// Kernel 1: C = h @ W, packed f32x2, BM=16, grid (64,3), 256 thr.
// mat==1 (W_r) also writes g_aR[h][row].
// =====================================================================
__global__ __launch_bounds__(256) void gemm_kernel(
    const float* __restrict__ H,
    const float* __restrict__ Wl,
    const float* __restrict__ Wr,
    const float* __restrict__ Wv)
{
    extern __shared__ float sm[];
    float* A_s = sm;              // [16][128]
    float* B_s = sm + 16 * 128;   // [128][128]

    const int tid = threadIdx.x;
    const int mat = blockIdx.y;
    const float* W = (mat == 0) ? Wl : ((mat == 1) ? Wr : Wv);
    float* C = (mat == 0) ? g_L : ((mat == 1) ? g_R : g_V);
    const int row0 = blockIdx.x * 16;

#pragma unroll
    for (int u = 0; u < 2; u++) {
        int id = tid + u * 256;
        int r = id >> 5, c4 = id & 31;
        *(float4*)&A_s[r * 128 + c4 * 4] =
            *(const float4*)&H[(row0 + r) * 128 + c4 * 4];
    }
#pragma unroll
    for (int u = 0; u < 16; u++) {
        int id = tid + u * 256;
        int r = id >> 5, c4 = id & 31;
        *(float4*)&B_s[r * 128 + c4 * 4] =
            *(const float4*)&W[r * OUTD + c4 * 4];
    }
    __syncthreads();

    const int ty = tid >> 5, tx = tid & 31;
    const int r0 = ty * 2;
    u64 c00 = 0ULL, c01 = 0ULL, c10 = 0ULL, c11 = 0ULL;

#pragma unroll 8
    for (int k = 0; k < 128; k++) {
        float a0 = A_s[(r0 + 0) * 128 + k];
        float a1 = A_s[(r0 + 1) * 128 + k];
        ulonglong2 b2 = *(const ulonglong2*)&B_s[k * 128 + tx * 4];
        u64 ap0 = f2pack(a0, a0);
        u64 ap1 = f2pack(a1, a1);
        c00 = f2fma(ap0, b2.x, c00); c01 = f2fma(ap0, b2.y, c01);
        c10 = f2fma(ap1, b2.x, c10); c11 = f2fma(ap1, b2.y, c11);
    }

    float2 u00 = f2unpack(c00), u01 = f2unpack(c01);
    float2 u10 = f2unpack(c10), u11 = f2unpack(c11);
    float a0c[4] = { u00.x, u00.y, u01.x, u01.y };
    float a1c[4] = { u10.x, u10.y, u11.x, u11.y };

    *(float4*)&C[(row0 + r0 + 0) * OUTD + tx * 4] =
        make_float4(a0c[0], a0c[1], a0c[2], a0c[3]);
    *(float4*)&C[(row0 + r0 + 1) * OUTD + tx * 4] =
        make_float4(a1c[0], a1c[1], a1c[2], a1c[3]);

    if (mat == 1) {
        const int hb = (tx & 7) * 4;
        float p0 = 0.f, p1 = 0.f;
#pragma unroll
        for (int c = 0; c < 4; c++) {
            float av = c_a[hb + c];
            p0 = fmaf(av, a0c[c], p0);
            p1 = fmaf(av, a1c[c], p1);
        }
#pragma unroll
        for (int o = 1; o < 8; o <<= 1) {
            p0 += __shfl_xor_sync(0xffffffffu, p0, o);
            p1 += __shfl_xor_sync(0xffffffffu, p1, o);
        }
        if ((tx & 7) == 0) {
            int h = tx >> 3;
            g_aR[h * NN + row0 + r0 + 0] = p0;
            g_aR[h * NN + row0 + r0 + 1] = p1;
        }
    }
}

// =====================================================================
// Kernel 2: 256 blocks x 256 threads (8 warps), 4 rows/block, TJ=32.
// 2 CTAs/SM. L register-resident.
// Score: warp (h=wid&3, jq=wid>>2); lane = jl + 16*rh:
//        j = jq*16+jl, rows rh*2..rh*2+1 (L in regs).
// Agg:   warp (h=wid&3, ds=wid>>2) -> cols h*32+ds*16..+16;
//        lane = rr*8+aj: row rr, j = jj*8+aj (jj 0..3).
// =====================================================================
__device__ __forceinline__ unsigned smem_u32(const void* p)
{
    unsigned r;
    asm("{ .reg .u64 t; cvta.to.shared.u64 t, %1; cvt.u32.u64 %0, t; }"
        : "=r"(r) : "l"(p));
    return r;
}
__device__ __forceinline__ void cp16(float* dst, const float* src)
{
    unsigned d = smem_u32(dst);
    asm volatile("cp.async.cg.shared.global [%0], [%1], 16;" :: "r"(d), "l"(src));
}

// smem layout (floats)
#define SM_R  0
#define SM_V  (SM_R + 2 * TJ * RPAD)        // 8448
#define SM_AR (SM_V + 2 * TJ * VPAD)        // 16896
#define SM_W  (SM_AR + 2 * 128)             // 17152
#define SM_SP (SM_W + 16 * WP)              // 17696 (2jq x 4row x 4h)
#define SM_O  (SM_SP + 32)                  // 17728
#define GAT_SMEM_FLOATS (SM_O + 4 * OPAD)   // 18256 (~73KB)

__device__ __forceinline__ void prefetch_tile(float* sm, int buf, int jb, int tid)
{
    float* Rd = sm + SM_R + buf * TJ * RPAD;
    float* Vd = sm + SM_V + buf * TJ * VPAD;
#pragma unroll
    for (int u = 0; u < 4; u++) {
        int id = tid + u * 256; int r = id >> 5, c4 = id & 31;
        cp16(&Rd[r * RPAD + c4 * 4], &g_R[(jb + r) * OUTD + c4 * 4]);
    }
#pragma unroll
    for (int u = 0; u < 4; u++) {
        int id = tid + u * 256; int r = id >> 5, c4 = id & 31;
        cp16(&Vd[r * VPAD + c4 * 4], &g_V[(jb + r) * OUTD + c4 * 4]);
    }
    if (tid < 32) {
        int h = tid >> 3, c4 = tid & 7;
        cp16(&sm[SM_AR + buf * 128 + h * 32 + c4 * 4],
             &g_aR[h * NN + jb + c4 * 4]);
    }
}

__global__ __launch_bounds__(256, 2) void gat_kernel(
    const int* __restrict__ adj,
    const float* __restrict__ ln_g,
    const float* __restrict__ ln_b,
    float* __restrict__ out)
{
    extern __shared__ float sm[];
    float* w_s   = sm + SM_W;
    float* sp_s  = sm + SM_SP;
    float* out_s = sm + SM_O;

    const int tid = threadIdx.x, lane = tid & 31, wid = tid >> 5;
    const int h  = wid & 3;
    const int jq = wid >> 2;        // score j-half / agg ds
    const int jl = lane & 15;       // score j within half
    const int rh = lane >> 4;       // score row-half
    const int jg = jq * 16 + jl;    // score j in tile
    const int rr = lane >> 3;       // agg row 0..3
    const int aj = lane & 7;        // agg j-lane 0..7
    const int colb = h * 32 + jq * 16;   // agg col base
    const int row0 = blockIdx.x * 4;

    // prefetch tile 0
    prefetch_tile(sm, 0, 0, tid);
    asm volatile("cp.async.commit_group;" ::: "memory");

    // L register-resident: 2 rows x 32 floats as u64 pairs
    u64 Lx[2][8], Ly[2][8];
#pragma unroll
    for (int r = 0; r < 2; r++) {
        const float* Lrow = &g_L[(row0 + rh * 2 + r) * OUTD + h * 32];
#pragma unroll
        for (int k = 0; k < 8; k++) {
            ulonglong2 t2 = *(const ulonglong2*)&Lrow[k * 4];
            Lx[r][k] = t2.x; Ly[r][k] = t2.y;
        }
    }
    // lin[r] = 0.6 * (a . L[row, h-slice])
    float lin[2];
#pragma unroll
    for (int r = 0; r < 2; r++) {
        u64 sa = 0ULL, sb = 0ULL;
#pragma unroll
        for (int k = 0; k < 8; k++) {
            sa = f2fma(a2c(2 * k), Lx[r][k], sa);
            sb = f2fma(a2c(2 * k + 1), Ly[r][k], sb);
        }
        float2 u = f2unpack(f2add(sa, sb));
        lin[r] = 0.6f * (u.x + u.y);
    }

    // adj for tile 0
    int av[2];
#pragma unroll
    for (int r = 0; r < 2; r++)
        av[r] = adj[(row0 + rh * 2 + r) * NN + jg];

    float s_acc[2] = { 0.f, 0.f };
    u64 acc[8];                      // agg: 1 row x 16 cols
#pragma unroll
    for (int c = 0; c < 8; c++) acc[c] = 0ULL;

    for (int t = 0; t < NT; t++) {
        const int b = t & 1;
        asm volatile("cp.async.wait_group 0;" ::: "memory");
        __syncthreads();   // tile t ready; prev agg done

        if (t + 1 < NT) {
            prefetch_tile(sm, b ^ 1, (t + 1) * TJ, tid);
            asm volatile("cp.async.commit_group;" ::: "memory");
        }
        int avn[2];
        if (t + 1 < NT) {
#pragma unroll
            for (int r = 0; r < 2; r++)
                avn[r] = adj[(row0 + rh * 2 + r) * NN + (t + 1) * TJ + jg];
        }

        // ================= SCORE =================
        {
            const float* Rrow = sm + SM_R + b * TJ * RPAD + jg * RPAD + h * 32;
            u64 sa0 = 0ULL, sb0 = 0ULL, sa1 = 0ULL, sb1 = 0ULL;
#pragma unroll
            for (int k = 0; k < 8; k++) {
                ulonglong2 r2 = *(const ulonglong2*)&Rrow[k * 4];
                sa0 = f2fma(a2c(2 * k),     f2add(Lx[0][k], r2.x) & ABSM, sa0);
                sb0 = f2fma(a2c(2 * k + 1), f2add(Ly[0][k], r2.y) & ABSM, sb0);
                sa1 = f2fma(a2c(2 * k),     f2add(Lx[1][k], r2.x) & ABSM, sa1);
                sb1 = f2fma(a2c(2 * k + 1), f2add(Ly[1][k], r2.y) & ABSM, sb1);
            }
            float ar6 = 0.6f * sm[SM_AR + b * 128 + h * 32 + jg];
            float2 u0 = f2unpack(f2add(sa0, sb0));
            float2 u1 = f2unpack(f2add(sa1, sb1));
            float e0 = fmaf(0.4f, u0.x + u0.y, lin[0] + ar6);
            float e1 = fmaf(0.4f, u1.x + u1.y, lin[1] + ar6);
            float w0 = av[0] ? __expf(e0) : 0.f;
            float w1 = av[1] ? __expf(e1) : 0.f;
            s_acc[0] += w0; s_acc[1] += w1;
            w_s[((rh * 2 + 0) * 4 + h) * WP + jg] = w0;
            w_s[((rh * 2 + 1) * 4 + h) * WP + jg] = w1;
        }
        av[0] = avn[0]; av[1] = avn[1];
        __syncthreads();   // weights ready

        // ================= AGG =================
        {
            const float* Vb = sm + SM_V + b * TJ * VPAD;
#pragma unroll
            for (int jj = 0; jj < 4; jj++) {
                int j = jj * 8 + aj;
                float w = w_s[(rr * 4 + h) * WP + j];
                u64 wp = f2pack(w, w);
                const float* vrow = &Vb[j * VPAD + colb];
                ulonglong2 v0 = *(const ulonglong2*)(vrow);
                ulonglong2 v1 = *(const ulonglong2*)(vrow + 4);
                ulonglong2 v2 = *(const ulonglong2*)(vrow + 8);
                ulonglong2 v3 = *(const ulonglong2*)(vrow + 12);
                acc[0] = f2fma(wp, v0.x, acc[0]); acc[1] = f2fma(wp, v0.y, acc[1]);
                acc[2] = f2fma(wp, v1.x, acc[2]); acc[3] = f2fma(wp, v1.y, acc[3]);
                acc[4] = f2fma(wp, v2.x, acc[4]); acc[5] = f2fma(wp, v2.y, acc[5]);
                acc[6] = f2fma(wp, v3.x, acc[6]); acc[7] = f2fma(wp, v3.y, acc[7]);
            }
        }
    }

    // ---- score sums: reduce over 16 jl lanes ----
#pragma unroll
    for (int r = 0; r < 2; r++) {
#pragma unroll
        for (int o = 1; o < 16; o <<= 1)
            s_acc[r] += __shfl_xor_sync(0xffffffffu, s_acc[r], o);
    }
    if (jl == 0) {
#pragma unroll
        for (int r = 0; r < 2; r++)
            sp_s[jq * 16 + (rh * 2 + r) * 4 + h] = s_acc[r];
    }
    __syncthreads();

    // ---- agg reduce over 8 aj lanes ----
#pragma unroll
    for (int c = 0; c < 8; c++) {
#pragma unroll
        for (int o = 1; o < 8; o <<= 1) {
            u64 other = __shfl_xor_sync(0xffffffffu, acc[c], o);
            acc[c] = f2add(acc[c], other);
        }
    }
    if (aj == 0) {
        float s = sp_s[rr * 4 + h] + sp_s[16 + rr * 4 + h];
        float inv = 1.0f / s;
#pragma unroll
        for (int c = 0; c < 8; c++) {
            float2 u = f2unpack(acc[c]);
            *(float2*)&out_s[rr * OPAD + colb + c * 2] =
                make_float2(u.x * inv, u.y * inv);
        }
    }
    __syncthreads();

    // ---- LayerNorm + ReLU: warps 0..3, warp = row ----
    if (wid < 4) {
        float4 x = *(const float4*)&out_s[wid * OPAD + lane * 4];
        float ssum = x.x + x.y + x.z + x.w;
        float sqs  = x.x * x.x + x.y * x.y + x.z * x.z + x.w * x.w;
#pragma unroll
        for (int o = 16; o; o >>= 1) {
            ssum += __shfl_xor_sync(0xffffffffu, ssum, o);
            sqs  += __shfl_xor_sync(0xffffffffu, sqs, o);
        }
        float mu   = ssum * (1.0f / 128.0f);
        float var  = sqs * (1.0f / 128.0f) - mu * mu;
        float rstd = rsqrtf(var + 1e-5f);
        float4 g4 = *(const float4*)&ln_g[lane * 4];
        float4 b4 = *(const float4*)&ln_b[lane * 4];
        float y0 = fmaxf((x.x - mu) * rstd * g4.x + b4.x, 0.f);
        float y1 = fmaxf((x.y - mu) * rstd * g4.y + b4.y, 0.f);
        float y2 = fmaxf((x.z - mu) * rstd * g4.z + b4.z, 0.f);
        float y3 = fmaxf((x.w - mu) * rstd * g4.w + b4.w, 0.f);
        *(float4*)&out[(row0 + wid) * OUTD + lane * 4] =
            make_float4(y0, y1, y2, y3);
    }
}

// =====================================================================
extern "C" void kernel_launch(void* const* d_in, const int* in_sizes, int n_in,
                              void* d_out, int out_size)
{
    const float* h   = (const float*)d_in[0];
    const int*   adj = (const int*)d_in[1];
    const float* Wl  = (const float*)d_in[2];
    const float* Wr  = (const float*)d_in[3];
    const float* Wv  = (const float*)d_in[4];
    const float* a   = (const float*)d_in[5];
    const float* g   = (const float*)d_in[6];
    const float* b   = (const float*)d_in[7];
    float* out = (float*)d_out;

    const int gemm_smem = (16 * 128 + 128 * 128) * (int)sizeof(float);   // 72KB
    const int gat_smem  = GAT_SMEM_FLOATS * (int)sizeof(float);          // ~73KB

    cudaFuncSetAttribute(gemm_kernel,
                         cudaFuncAttributeMaxDynamicSharedMemorySize, gemm_smem);
    cudaFuncSetAttribute(gat_kernel,
                         cudaFuncAttributeMaxDynamicSharedMemorySize, gat_smem);

    cudaMemcpyToSymbolAsync(c_a, a, 32 * sizeof(float), 0,
                            cudaMemcpyDeviceToDevice, 0);

    gemm_kernel<<<dim3(64, 3), 256, gemm_smem>>>(h, Wl, Wr, Wv);
    gat_kernel<<<256, 256, gat_smem>>>(adj, g, b, out);
}

// round 8
// speedup vs baseline: 1.2305x; 1.2305x over previous
#include <cuda_runtime.h>
#include <math.h>

#define NN   1024
#define OUTD 128
#define TJ   64
#define NT   16
#define RPAD 132
#define VPAD 132
#define LPAD 132
#define OPAD 132
#define WP   67

#define ABSM 0x7FFFFFFF7FFFFFFFULL

typedef unsigned long long u64;

// ---- scratch ----
__device__ __align__(16) float g_L[NN * OUTD];
__device__ __align__(16) float g_R[NN * OUTD];
__device__ __align__(16) float g_V[NN * OUTD];
__device__ __align__(16) float g_aR[4 * NN];   // [h][j]

__constant__ __align__(16) float c_a[32];

// ---- f32x2 helpers ----
__device__ __forceinline__ u64 f2add(u64 a, u64 b) {
    u64 d; asm("add.rn.f32x2 %0,%1,%2;" : "=l"(d) : "l"(a), "l"(b)); return d;
}
__device__ __forceinline__ u64 f2fma(u64 a, u64 b, u64 c) {
    u64 d; asm("fma.rn.f32x2 %0,%1,%2,%3;" : "=l"(d) : "l"(a), "l"(b), "l"(c)); return d;
}
__device__ __forceinline__ u64 f2pack(float x, float y) {
    u64 d; asm("mov.b64 %0,{%1,%2};" : "=l"(d) : "f"(x), "f"(y)); return d;
}
__device__ __forceinline__ float2 f2unpack(u64 v) {
    float x, y; asm("mov.b64 {%0,%1},%2;" : "=f"(x), "=f"(y) : "l"(v));
    return make_float2(x, y);
}
__device__ __forceinline__ u64 a2c(int k) { return *(const u64*)&c_a[2 * k]; }

// =====================================================================
// Kernel 1: C = h @ W, packed f32x2, BM=16, grid (64,3), 256 thr.
// mat==1 (W_r) also writes g_aR[h][row].
// =====================================================================
__global__ __launch_bounds__(256) void gemm_kernel(
    const float* __restrict__ H,
    const float* __restrict__ Wl,
    const float* __restrict__ Wr,
    const float* __restrict__ Wv)
{
    extern __shared__ float sm[];
    float* A_s = sm;              // [16][128]
    float* B_s = sm + 16 * 128;   // [128][128]

    const int tid = threadIdx.x;
    const int mat = blockIdx.y;
    const float* W = (mat == 0) ? Wl : ((mat == 1) ? Wr : Wv);
    float* C = (mat == 0) ? g_L : ((mat == 1) ? g_R : g_V);
    const int row0 = blockIdx.x * 16;

#pragma unroll
    for (int u = 0; u < 2; u++) {
        int id = tid + u * 256;
        int r = id >> 5, c4 = id & 31;
        *(float4*)&A_s[r * 128 + c4 * 4] =
            *(const float4*)&H[(row0 + r) * 128 + c4 * 4];
    }
#pragma unroll
    for (int u = 0; u < 16; u++) {
        int id = tid + u * 256;
        int r = id >> 5, c4 = id & 31;
        *(float4*)&B_s[r * 128 + c4 * 4] =
            *(const float4*)&W[r * OUTD + c4 * 4];
    }
    __syncthreads();

    const int ty = tid >> 5, tx = tid & 31;
    const int r0 = ty * 2;
    u64 c00 = 0ULL, c01 = 0ULL, c10 = 0ULL, c11 = 0ULL;

#pragma unroll 8
    for (int k = 0; k < 128; k++) {
        float a0 = A_s[(r0 + 0) * 128 + k];
        float a1 = A_s[(r0 + 1) * 128 + k];
        ulonglong2 b2 = *(const ulonglong2*)&B_s[k * 128 + tx * 4];
        u64 ap0 = f2pack(a0, a0);
        u64 ap1 = f2pack(a1, a1);
        c00 = f2fma(ap0, b2.x, c00); c01 = f2fma(ap0, b2.y, c01);
        c10 = f2fma(ap1, b2.x, c10); c11 = f2fma(ap1, b2.y, c11);
    }

    float2 u00 = f2unpack(c00), u01 = f2unpack(c01);
    float2 u10 = f2unpack(c10), u11 = f2unpack(c11);
    float a0c[4] = { u00.x, u00.y, u01.x, u01.y };
    float a1c[4] = { u10.x, u10.y, u11.x, u11.y };

    *(float4*)&C[(row0 + r0 + 0) * OUTD + tx * 4] =
        make_float4(a0c[0], a0c[1], a0c[2], a0c[3]);
    *(float4*)&C[(row0 + r0 + 1) * OUTD + tx * 4] =
        make_float4(a1c[0], a1c[1], a1c[2], a1c[3]);

    if (mat == 1) {
        const int hb = (tx & 7) * 4;
        float p0 = 0.f, p1 = 0.f;
#pragma unroll
        for (int c = 0; c < 4; c++) {
            float av = c_a[hb + c];
            p0 = fmaf(av, a0c[c], p0);
            p1 = fmaf(av, a1c[c], p1);
        }
#pragma unroll
        for (int o = 1; o < 8; o <<= 1) {
            p0 += __shfl_xor_sync(0xffffffffu, p0, o);
            p1 += __shfl_xor_sync(0xffffffffu, p1, o);
        }
        if ((tx & 7) == 0) {
            int h = tx >> 3;
            g_aR[h * NN + row0 + r0 + 0] = p0;
            g_aR[h * NN + row0 + r0 + 1] = p1;
        }
    }
}

// =====================================================================
// Kernel 2: 128 blocks x 512 threads (16 warps), 8 rows/block, TJ=64.
// Software-pipelined: ONE __syncthreads per tile; agg lags score by one
// tile. w_s/R/aR double-buffered, V triple-buffered.
// Score: warp (h=wid&3, jq=wid>>2); lane: jg = jq*16+(lane>>1),
//        rh = lane&1 -> rows rh*4..rh*4+3.
// Agg:   warp (h=wid&3, jq=wid>>2) -> cols colb=h*32+jq*8 (8 cols);
//        lane: aj = lane>>1 (j = jj*16+aj), rh -> rows rh*4..+3.
// =====================================================================
__device__ __forceinline__ unsigned smem_u32(const void* p)
{
    unsigned r;
    asm("{ .reg .u64 t; cvta.to.shared.u64 t, %1; cvt.u32.u64 %0, t; }"
        : "=r"(r) : "l"(p));
    return r;
}
__device__ __forceinline__ void cp16(float* dst, const float* src)
{
    unsigned d = smem_u32(dst);
    asm volatile("cp.async.cg.shared.global [%0], [%1], 16;" :: "r"(d), "l"(src));
}

// smem layout (floats)
#define SM_R  0
#define SM_V  (SM_R + 2 * TJ * RPAD)        // 16896
#define SM_AR (SM_V + 3 * TJ * VPAD)        // 42240
#define SM_W  (SM_AR + 2 * 256)             // 42752
#define SM_L  (SM_W + 2 * 32 * WP)          // 47040
#define SM_SP (SM_L + 8 * LPAD)             // 48096
#define SM_O  (SM_SP + 128)                 // 48224
#define GAT_SMEM_FLOATS (SM_O + 8 * OPAD)   // 49280 (~197KB)

__device__ __forceinline__ void prefetch_tile(float* sm, int rbuf, int vbuf,
                                              int jb, int tid)
{
    float* Rd = sm + SM_R + rbuf * TJ * RPAD;
    float* Vd = sm + SM_V + vbuf * TJ * VPAD;
#pragma unroll
    for (int u = 0; u < 4; u++) {
        int id = tid + u * 512; int r = id >> 5, c4 = id & 31;
        cp16(&Rd[r * RPAD + c4 * 4], &g_R[(jb + r) * OUTD + c4 * 4]);
    }
#pragma unroll
    for (int u = 0; u < 4; u++) {
        int id = tid + u * 512; int r = id >> 5, c4 = id & 31;
        cp16(&Vd[r * VPAD + c4 * 4], &g_V[(jb + r) * OUTD + c4 * 4]);
    }
    if (tid < 64) {
        int h = tid >> 4, c4 = tid & 15;
        cp16(&sm[SM_AR + rbuf * 256 + h * TJ + c4 * 4],
             &g_aR[h * NN + jb + c4 * 4]);
    }
}

__global__ __launch_bounds__(512, 1) void gat_kernel(
    const int* __restrict__ adj,
    const float* __restrict__ ln_g,
    const float* __restrict__ ln_b,
    float* __restrict__ out)
{
    extern __shared__ float sm[];
    float* w_s   = sm + SM_W;
    float* L_s   = sm + SM_L;
    float* sp_s  = sm + SM_SP;
    float* out_s = sm + SM_O;

    const int tid = threadIdx.x, lane = tid & 31, wid = tid >> 5;
    const int h  = wid & 3;
    const int jq = wid >> 2;
    const int jg = jq * 16 + (lane >> 1);   // score j in tile
    const int rh = lane & 1;                // row half (both roles)
    const int aj = lane >> 1;               // agg j-lane 0..15
    const int colb = h * 32 + jq * 8;       // agg col base (8 cols)
    const int row0 = blockIdx.x * 8;

    // prologue: prefetch tile 0, stage L
    prefetch_tile(sm, 0, 0, 0, tid);
    asm volatile("cp.async.commit_group;" ::: "memory");
    if (tid < 256) {
        int r = tid >> 5, c4 = tid & 31;
        *(float4*)&L_s[r * LPAD + c4 * 4] =
            *(const float4*)&g_L[(row0 + r) * OUTD + c4 * 4];
    }
    __syncthreads();   // L_s ready

    // lin[ii] = 0.6 * (a . L[row, h-slice])
    float lin[4];
#pragma unroll
    for (int ii = 0; ii < 4; ii++) {
        const float* Lrow = &L_s[(rh * 4 + ii) * LPAD + h * 32];
        u64 sa = 0ULL, sb = 0ULL;
#pragma unroll
        for (int k = 0; k < 8; k++) {
            ulonglong2 l2 = *(const ulonglong2*)&Lrow[k * 4];
            sa = f2fma(a2c(2 * k), l2.x, sa);
            sb = f2fma(a2c(2 * k + 1), l2.y, sb);
        }
        float2 u = f2unpack(f2add(sa, sb));
        lin[ii] = 0.6f * (u.x + u.y);
    }

    // adj for tile 0
    int av[4];
#pragma unroll
    for (int ii = 0; ii < 4; ii++)
        av[ii] = adj[(row0 + rh * 4 + ii) * NN + jg];

    float s_acc[4] = { 0.f, 0.f, 0.f, 0.f };
    u64 acc[4][4];
#pragma unroll
    for (int r = 0; r < 4; r++)
#pragma unroll
        for (int c = 0; c < 4; c++) acc[r][c] = 0ULL;

    for (int t = 0; t < NT; t++) {
        const int rb = t & 1;
        const int vb = t % 3;

        asm volatile("cp.async.wait_group 0;" ::: "memory");
        __syncthreads();   // tile t data ready; w[t-1] visible; old bufs free

        if (t + 1 < NT) {
            prefetch_tile(sm, rb ^ 1, (t + 1) % 3, (t + 1) * TJ, tid);
            asm volatile("cp.async.commit_group;" ::: "memory");
        }
        int avn[4];
        if (t + 1 < NT) {
#pragma unroll
            for (int ii = 0; ii < 4; ii++)
                avn[ii] = adj[(row0 + rh * 4 + ii) * NN + (t + 1) * TJ + jg];
        }

        // ================= AGG (tile t-1) =================
        if (t > 0) {
            const float* Vb = sm + SM_V + ((t - 1) % 3) * TJ * VPAD;
            const float* wb = w_s + ((t - 1) & 1) * 32 * WP;
#pragma unroll
            for (int jj = 0; jj < 4; jj++) {
                int j = jj * 16 + aj;
                const float* vrow = &Vb[j * VPAD + colb];
                ulonglong2 v0 = *(const ulonglong2*)(vrow);
                ulonglong2 v1 = *(const ulonglong2*)(vrow + 4);
#pragma unroll
                for (int r = 0; r < 4; r++) {
                    float w = wb[((rh * 4 + r) * 4 + h) * WP + j];
                    u64 wp = f2pack(w, w);
                    acc[r][0] = f2fma(wp, v0.x, acc[r][0]);
                    acc[r][1] = f2fma(wp, v0.y, acc[r][1]);
                    acc[r][2] = f2fma(wp, v1.x, acc[r][2]);
                    acc[r][3] = f2fma(wp, v1.y, acc[r][3]);
                }
            }
        }

        // ================= SCORE (tile t) =================
        {
            const float* Rrow = sm + SM_R + rb * TJ * RPAD + jg * RPAD + h * 32;
            float* wb = w_s + rb * 32 * WP;
            u64 sa[4], sb[4];
#pragma unroll
            for (int ii = 0; ii < 4; ii++) { sa[ii] = 0ULL; sb[ii] = 0ULL; }
#pragma unroll
            for (int k = 0; k < 8; k++) {
                ulonglong2 r2 = *(const ulonglong2*)&Rrow[k * 4];
#pragma unroll
                for (int ii = 0; ii < 4; ii++) {
                    const ulonglong2 l2 = *(const ulonglong2*)
                        &L_s[(rh * 4 + ii) * LPAD + h * 32 + k * 4];
                    sa[ii] = f2fma(a2c(2 * k),
                                   f2add(l2.x, r2.x) & ABSM, sa[ii]);
                    sb[ii] = f2fma(a2c(2 * k + 1),
                                   f2add(l2.y, r2.y) & ABSM, sb[ii]);
                }
            }
            float ar6 = 0.6f * sm[SM_AR + rb * 256 + h * TJ + jg];
#pragma unroll
            for (int ii = 0; ii < 4; ii++) {
                float2 u = f2unpack(f2add(sa[ii], sb[ii]));
                float e = fmaf(0.4f, u.x + u.y, lin[ii] + ar6);
                float w = av[ii] ? __expf(e) : 0.f;
                s_acc[ii] += w;
                wb[((rh * 4 + ii) * 4 + h) * WP + jg] = w;
            }
        }
#pragma unroll
        for (int ii = 0; ii < 4; ii++) av[ii] = avn[ii];
    }

    // drain: agg for the last tile
    __syncthreads();
    {
        const float* Vb = sm + SM_V + ((NT - 1) % 3) * TJ * VPAD;
        const float* wb = w_s + ((NT - 1) & 1) * 32 * WP;
#pragma unroll
        for (int jj = 0; jj < 4; jj++) {
            int j = jj * 16 + aj;
            const float* vrow = &Vb[j * VPAD + colb];
            ulonglong2 v0 = *(const ulonglong2*)(vrow);
            ulonglong2 v1 = *(const ulonglong2*)(vrow + 4);
#pragma unroll
            for (int r = 0; r < 4; r++) {
                float w = wb[((rh * 4 + r) * 4 + h) * WP + j];
                u64 wp = f2pack(w, w);
                acc[r][0] = f2fma(wp, v0.x, acc[r][0]);
                acc[r][1] = f2fma(wp, v0.y, acc[r][1]);
                acc[r][2] = f2fma(wp, v1.x, acc[r][2]);
                acc[r][3] = f2fma(wp, v1.y, acc[r][3]);
            }
        }
    }

    // ---- score sums: reduce over the 16 j-lanes (stride-2 groups) ----
#pragma unroll
    for (int ii = 0; ii < 4; ii++) {
#pragma unroll
        for (int o = 2; o < 32; o <<= 1)
            s_acc[ii] += __shfl_xor_sync(0xffffffffu, s_acc[ii], o);
    }
    if ((lane >> 1) == 0) {
#pragma unroll
        for (int ii = 0; ii < 4; ii++)
            sp_s[jq * 32 + (rh * 4 + ii) * 4 + h] = s_acc[ii];
    }
    __syncthreads();

    // ---- agg reduce over 16 aj lanes ----
#pragma unroll
    for (int r = 0; r < 4; r++)
#pragma unroll
        for (int c = 0; c < 4; c++) {
#pragma unroll
            for (int o = 2; o < 32; o <<= 1) {
                u64 other = __shfl_xor_sync(0xffffffffu, acc[r][c], o);
                acc[r][c] = f2add(acc[r][c], other);
            }
        }
    if (aj == 0) {
#pragma unroll
        for (int r = 0; r < 4; r++) {
            int row = rh * 4 + r;
            float s = sp_s[0 * 32 + row * 4 + h] + sp_s[1 * 32 + row * 4 + h]
                    + sp_s[2 * 32 + row * 4 + h] + sp_s[3 * 32 + row * 4 + h];
            float inv = 1.0f / s;
#pragma unroll
            for (int c = 0; c < 4; c++) {
                float2 u = f2unpack(acc[r][c]);
                *(float2*)&out_s[row * OPAD + colb + c * 2] =
                    make_float2(u.x * inv, u.y * inv);
            }
        }
    }
    __syncthreads();

    // ---- LayerNorm + ReLU: warps 0..7, warp = row ----
    if (wid < 8) {
        float4 x = *(const float4*)&out_s[wid * OPAD + lane * 4];
        float ssum = x.x + x.y + x.z + x.w;
        float sqs  = x.x * x.x + x.y * x.y + x.z * x.z + x.w * x.w;
#pragma unroll
        for (int o = 16; o; o >>= 1) {
            ssum += __shfl_xor_sync(0xffffffffu, ssum, o);
            sqs  += __shfl_xor_sync(0xffffffffu, sqs, o);
        }
        float mu   = ssum * (1.0f / 128.0f);
        float var  = sqs * (1.0f / 128.0f) - mu * mu;
        float rstd = rsqrtf(var + 1e-5f);
        float4 g4 = *(const float4*)&ln_g[lane * 4];
        float4 b4 = *(const float4*)&ln_b[lane * 4];
        float y0 = fmaxf((x.x - mu) * rstd * g4.x + b4.x, 0.f);
        float y1 = fmaxf((x.y - mu) * rstd * g4.y + b4.y, 0.f);
        float y2 = fmaxf((x.z - mu) * rstd * g4.z + b4.z, 0.f);
        float y3 = fmaxf((x.w - mu) * rstd * g4.w + b4.w, 0.f);
        *(float4*)&out[(row0 + wid) * OUTD + lane * 4] =
            make_float4(y0, y1, y2, y3);
    }
}

// =====================================================================
extern "C" void kernel_launch(void* const* d_in, const int* in_sizes, int n_in,
                              void* d_out, int out_size)
{
    const float* h   = (const float*)d_in[0];
    const int*   adj = (const int*)d_in[1];
    const float* Wl  = (const float*)d_in[2];
    const float* Wr  = (const float*)d_in[3];
    const float* Wv  = (const float*)d_in[4];
    const float* a   = (const float*)d_in[5];
    const float* g   = (const float*)d_in[6];
    const float* b   = (const float*)d_in[7];
    float* out = (float*)d_out;

    const int gemm_smem = (16 * 128 + 128 * 128) * (int)sizeof(float);   // 72KB
    const int gat_smem  = GAT_SMEM_FLOATS * (int)sizeof(float);          // ~197KB

    cudaFuncSetAttribute(gemm_kernel,
                         cudaFuncAttributeMaxDynamicSharedMemorySize, gemm_smem);
    cudaFuncSetAttribute(gat_kernel,
                         cudaFuncAttributeMaxDynamicSharedMemorySize, gat_smem);

    cudaMemcpyToSymbolAsync(c_a, a, 32 * sizeof(float), 0,
                            cudaMemcpyDeviceToDevice, 0);

    gemm_kernel<<<dim3(64, 3), 256, gemm_smem>>>(h, Wl, Wr, Wv);
    gat_kernel<<<128, 512, gat_smem>>>(adj, g, b, out);
}